// round 2
// baseline (speedup 1.0000x reference)
#include <cuda_runtime.h>

// SimpleNetworkAD: 480 independent 1->20->20->20->1 tanh MLPs, B=16384.
// R2: (a) weights/biases pre-duplicated in SMEM as 64-bit {w,w} pairs so the
//     inner loop is LDS.64 + fma.rn.f32x2 only (no broadcast MOVs);
//     (b) HW tanh.approx for layers 1-2 (errors damped downstream), accurate
//     ex2/rcp tanh for layer 3, keeping MUFU below the FMA-pipe budget.

#define GNODE 480
#define HDIM  20
#define TPB   256

typedef unsigned long long u64;

__device__ __forceinline__ u64 f2_pack(float lo, float hi) {
    u64 r; asm("mov.b64 %0, {%1, %2};" : "=l"(r) : "f"(lo), "f"(hi)); return r;
}
__device__ __forceinline__ void f2_unpack(u64 v, float& lo, float& hi) {
    asm("mov.b64 {%0, %1}, %2;" : "=f"(lo), "=f"(hi) : "l"(v));
}
__device__ __forceinline__ u64 f2_fma(u64 a, u64 b, u64 c) {
    u64 d; asm("fma.rn.f32x2 %0, %1, %2, %3;" : "=l"(d) : "l"(a), "l"(b), "l"(c)); return d;
}
__device__ __forceinline__ u64 f2_mul(u64 a, u64 b) {
    u64 d; asm("mul.rn.f32x2 %0, %1, %2;" : "=l"(d) : "l"(a), "l"(b)); return d;
}
__device__ __forceinline__ float ex2a(float x) {
    float r; asm("ex2.approx.f32 %0, %1;" : "=f"(r) : "f"(x)); return r;
}
__device__ __forceinline__ float rcpa(float x) {
    float r; asm("rcp.approx.f32 %0, %1;" : "=f"(r) : "f"(x)); return r;
}
__device__ __forceinline__ float tanha(float x) {
    float r; asm("tanh.approx.f32 %0, %1;" : "=f"(r) : "f"(x)); return r;
}

// Fast tanh: 1 MUFU per scalar (HW tanh). Used for layers 1-2.
__device__ __forceinline__ u64 f2_tanh_fast(u64 x) {
    float a, b; f2_unpack(x, a, b);
    return f2_pack(tanha(a), tanha(b));
}

// Accurate tanh (~1e-6): 2 MUFU per scalar. Used for layer 3 (feeds output).
__device__ __forceinline__ u64 f2_tanh_acc(u64 x, u64 c_l2e2, u64 c_m2, u64 c_p1) {
    u64 t = f2_mul(x, c_l2e2);               // 2*log2(e)*x
    float t0, t1; f2_unpack(t, t0, t1);
    float e0 = ex2a(t0), e1 = ex2a(t1);
    float r0 = rcpa(e0 + 1.0f);
    float r1 = rcpa(e1 + 1.0f);
    return f2_fma(f2_pack(r0, r1), c_m2, c_p1);  // 1 - 2/(1+e^{2x})
}

__global__ void __launch_bounds__(TPB)
simple_network_ad_kernel(const float* __restrict__ x,
                         const float* __restrict__ W1, const float* __restrict__ B1,
                         const float* __restrict__ W2, const float* __restrict__ B2,
                         const float* __restrict__ W3, const float* __restrict__ B3,
                         const float* __restrict__ W4, const float* __restrict__ B4,
                         float* __restrict__ out, int n_b)
{
    // All weights/biases duplicated into {w,w} 64-bit pairs -> LDS.64 feeds
    // FFMA2 directly, no per-FMA broadcast MOVs.
    __shared__ u64 sW1[HDIM], sB1[HDIM];
    __shared__ u64 sW2[HDIM * HDIM], sB2[HDIM];
    __shared__ u64 sW3[HDIM * HDIM], sB3[HDIM];
    __shared__ u64 sW4[HDIM];
    __shared__ u64 sB4;

    const int g   = blockIdx.y;
    const int tid = threadIdx.x;

    if (tid < HDIM) {
        float w1 = W1[g * HDIM + tid];  sW1[tid] = f2_pack(w1, w1);
        float b1 = B1[g * HDIM + tid];  sB1[tid] = f2_pack(b1, b1);
        float b2 = B2[g * HDIM + tid];  sB2[tid] = f2_pack(b2, b2);
        float b3 = B3[g * HDIM + tid];  sB3[tid] = f2_pack(b3, b3);
        float w4 = W4[g * HDIM + tid];  sW4[tid] = f2_pack(w4, w4);
    }
    if (tid == 0) { float b4 = B4[g]; sB4 = f2_pack(b4, b4); }
    for (int i = tid; i < HDIM * HDIM; i += TPB) {
        float w2 = W2[g * HDIM * HDIM + i];  sW2[i] = f2_pack(w2, w2);
        float w3 = W3[g * HDIM * HDIM + i];  sW3[i] = f2_pack(w3, w3);
    }
    __syncthreads();

    const int b0 = blockIdx.x * (TPB * 2) + tid;
    const int b1 = b0 + TPB;
    if (b0 >= n_b) return;

    const u64 c_l2e2 = f2_pack(2.8853900817779268f, 2.8853900817779268f);
    const u64 c_m2   = f2_pack(-2.0f, -2.0f);
    const u64 c_p1   = f2_pack(1.0f, 1.0f);

    float x0 = x[(size_t)b0 * GNODE + g];
    float x1 = (b1 < n_b) ? x[(size_t)b1 * GNODE + g] : 0.0f;
    u64 xin = f2_pack(x0, x1);

    u64 h[HDIM], acc[HDIM];

    // Layer 1: h = tanh(x * W1 + b1)   (fast tanh)
    #pragma unroll
    for (int i = 0; i < HDIM; i++)
        h[i] = f2_tanh_fast(f2_fma(xin, sW1[i], sB1[i]));

    // Layer 2: h = tanh(h @ W2 + b2)   (fast tanh)
    #pragma unroll
    for (int l = 0; l < HDIM; l++) acc[l] = sB2[l];
    #pragma unroll
    for (int k = 0; k < HDIM; k++) {
        u64 hk = h[k];
        #pragma unroll
        for (int l = 0; l < HDIM; l++)
            acc[l] = f2_fma(hk, sW2[k * HDIM + l], acc[l]);
    }
    #pragma unroll
    for (int l = 0; l < HDIM; l++) h[l] = f2_tanh_fast(acc[l]);

    // Layer 3: h = tanh(h @ W3 + b3)   (accurate tanh - feeds output directly)
    #pragma unroll
    for (int l = 0; l < HDIM; l++) acc[l] = sB3[l];
    #pragma unroll
    for (int k = 0; k < HDIM; k++) {
        u64 hk = h[k];
        #pragma unroll
        for (int l = 0; l < HDIM; l++)
            acc[l] = f2_fma(hk, sW3[k * HDIM + l], acc[l]);
    }
    #pragma unroll
    for (int l = 0; l < HDIM; l++) h[l] = f2_tanh_acc(acc[l], c_l2e2, c_m2, c_p1);

    // Layer 4: out = h . W4 + b4
    u64 o = sB4;
    #pragma unroll
    for (int k = 0; k < HDIM; k++)
        o = f2_fma(h[k], sW4[k], o);

    float o0, o1;
    f2_unpack(o, o0, o1);
    out[(size_t)b0 * GNODE + g] = o0;
    if (b1 < n_b) out[(size_t)b1 * GNODE + g] = o1;
}

extern "C" void kernel_launch(void* const* d_in, const int* in_sizes, int n_in,
                              void* d_out, int out_size)
{
    const float* x  = (const float*)d_in[0];
    const float* W1 = (const float*)d_in[1];
    const float* B1 = (const float*)d_in[2];
    const float* W2 = (const float*)d_in[3];
    const float* B2 = (const float*)d_in[4];
    const float* W3 = (const float*)d_in[5];
    const float* B3 = (const float*)d_in[6];
    const float* W4 = (const float*)d_in[7];
    const float* B4 = (const float*)d_in[8];
    float* out = (float*)d_out;

    int n_b = in_sizes[0] / GNODE;                 // 16384
    int chunks = (n_b + TPB * 2 - 1) / (TPB * 2);  // 32
    dim3 grid(chunks, GNODE);
    simple_network_ad_kernel<<<grid, TPB>>>(x, W1, B1, W2, B2, W3, B3, W4, B4, out, n_b);
}

// round 3
// speedup vs baseline: 1.2513x; 1.2513x over previous
#include <cuda_runtime.h>

// SimpleNetworkAD: 480 independent 1->20->20->20->1 tanh MLPs, B=16384.
// R3: 4 batch points per thread (two f32x2 packs) so each LDS.64 weight load
//     feeds 2 FFMA2s -> smem pipe drops from 92% to ~45%, fma pipe becomes
//     the binder (~350K cyc/SMSP). Full HW tanh.approx (evidence from R2:
//     approx layers cost only ~3e-6 rel_err).

#define GNODE 480
#define HDIM  20
#define TPB   256
#define PTS   4              // batch points per thread (2 f32x2 packs)

typedef unsigned long long u64;

__device__ __forceinline__ u64 f2_pack(float lo, float hi) {
    u64 r; asm("mov.b64 %0, {%1, %2};" : "=l"(r) : "f"(lo), "f"(hi)); return r;
}
__device__ __forceinline__ void f2_unpack(u64 v, float& lo, float& hi) {
    asm("mov.b64 {%0, %1}, %2;" : "=f"(lo), "=f"(hi) : "l"(v));
}
__device__ __forceinline__ u64 f2_fma(u64 a, u64 b, u64 c) {
    u64 d; asm("fma.rn.f32x2 %0, %1, %2, %3;" : "=l"(d) : "l"(a), "l"(b), "l"(c)); return d;
}
__device__ __forceinline__ float tanha(float x) {
    float r; asm("tanh.approx.f32 %0, %1;" : "=f"(r) : "f"(x)); return r;
}
__device__ __forceinline__ u64 f2_tanh(u64 x) {
    float a, b; f2_unpack(x, a, b);
    return f2_pack(tanha(a), tanha(b));
}

__global__ void __launch_bounds__(TPB, 1)
simple_network_ad_kernel(const float* __restrict__ x,
                         const float* __restrict__ W1, const float* __restrict__ B1,
                         const float* __restrict__ W2, const float* __restrict__ B2,
                         const float* __restrict__ W3, const float* __restrict__ B3,
                         const float* __restrict__ W4, const float* __restrict__ B4,
                         float* __restrict__ out, int n_b)
{
    // Weights/biases duplicated into {w,w} 64-bit pairs: LDS.64 feeds FFMA2.
    __shared__ u64 sW1[HDIM], sB1[HDIM];
    __shared__ u64 sW2[HDIM * HDIM], sB2[HDIM];
    __shared__ u64 sW3[HDIM * HDIM], sB3[HDIM];
    __shared__ u64 sW4[HDIM];
    __shared__ u64 sB4;

    const int g   = blockIdx.y;
    const int tid = threadIdx.x;

    if (tid < HDIM) {
        float w1 = W1[g * HDIM + tid];  sW1[tid] = f2_pack(w1, w1);
        float b1 = B1[g * HDIM + tid];  sB1[tid] = f2_pack(b1, b1);
        float b2 = B2[g * HDIM + tid];  sB2[tid] = f2_pack(b2, b2);
        float b3 = B3[g * HDIM + tid];  sB3[tid] = f2_pack(b3, b3);
        float w4 = W4[g * HDIM + tid];  sW4[tid] = f2_pack(w4, w4);
    }
    if (tid == 0) { float b4 = B4[g]; sB4 = f2_pack(b4, b4); }
    for (int i = tid; i < HDIM * HDIM; i += TPB) {
        float w2 = W2[g * HDIM * HDIM + i];  sW2[i] = f2_pack(w2, w2);
        float w3 = W3[g * HDIM * HDIM + i];  sW3[i] = f2_pack(w3, w3);
    }
    __syncthreads();

    // 4 points per thread: b0, b0+TPB, b0+2*TPB, b0+3*TPB
    const int b0 = blockIdx.x * (TPB * PTS) + tid;
    if (b0 >= n_b) return;
    const int bA = b0;
    const int bB = b0 + TPB;
    const int bC = b0 + 2 * TPB;
    const int bD = b0 + 3 * TPB;
    const bool fullTail = (bD < n_b);

    float xA = x[(size_t)bA * GNODE + g];
    float xB = (bB < n_b) ? x[(size_t)bB * GNODE + g] : 0.0f;
    float xC = (bC < n_b) ? x[(size_t)bC * GNODE + g] : 0.0f;
    float xD = (bD < n_b) ? x[(size_t)bD * GNODE + g] : 0.0f;
    u64 xin0 = f2_pack(xA, xB);
    u64 xin1 = f2_pack(xC, xD);

    u64 h0[HDIM], h1[HDIM];
    u64 a0[HDIM], a1[HDIM];

    // Layer 1: h = tanh(x * W1 + b1)
    #pragma unroll
    for (int i = 0; i < HDIM; i++) {
        u64 w = sW1[i], b = sB1[i];
        h0[i] = f2_tanh(f2_fma(xin0, w, b));
        h1[i] = f2_tanh(f2_fma(xin1, w, b));
    }

    // Layer 2: h = tanh(h @ W2 + b2)
    #pragma unroll
    for (int l = 0; l < HDIM; l++) { u64 b = sB2[l]; a0[l] = b; a1[l] = b; }
    #pragma unroll
    for (int k = 0; k < HDIM; k++) {
        u64 hk0 = h0[k], hk1 = h1[k];
        #pragma unroll
        for (int l = 0; l < HDIM; l++) {
            u64 w = sW2[k * HDIM + l];
            a0[l] = f2_fma(hk0, w, a0[l]);
            a1[l] = f2_fma(hk1, w, a1[l]);
        }
    }
    #pragma unroll
    for (int l = 0; l < HDIM; l++) { h0[l] = f2_tanh(a0[l]); h1[l] = f2_tanh(a1[l]); }

    // Layer 3: h = tanh(h @ W3 + b3)
    #pragma unroll
    for (int l = 0; l < HDIM; l++) { u64 b = sB3[l]; a0[l] = b; a1[l] = b; }
    #pragma unroll
    for (int k = 0; k < HDIM; k++) {
        u64 hk0 = h0[k], hk1 = h1[k];
        #pragma unroll
        for (int l = 0; l < HDIM; l++) {
            u64 w = sW3[k * HDIM + l];
            a0[l] = f2_fma(hk0, w, a0[l]);
            a1[l] = f2_fma(hk1, w, a1[l]);
        }
    }
    #pragma unroll
    for (int l = 0; l < HDIM; l++) { h0[l] = f2_tanh(a0[l]); h1[l] = f2_tanh(a1[l]); }

    // Layer 4: out = h . W4 + b4
    u64 o0 = sB4, o1 = sB4;
    #pragma unroll
    for (int k = 0; k < HDIM; k++) {
        u64 w = sW4[k];
        o0 = f2_fma(h0[k], w, o0);
        o1 = f2_fma(h1[k], w, o1);
    }

    float oA, oB, oC, oD;
    f2_unpack(o0, oA, oB);
    f2_unpack(o1, oC, oD);
    if (fullTail) {
        out[(size_t)bA * GNODE + g] = oA;
        out[(size_t)bB * GNODE + g] = oB;
        out[(size_t)bC * GNODE + g] = oC;
        out[(size_t)bD * GNODE + g] = oD;
    } else {
        out[(size_t)bA * GNODE + g] = oA;
        if (bB < n_b) out[(size_t)bB * GNODE + g] = oB;
        if (bC < n_b) out[(size_t)bC * GNODE + g] = oC;
        if (bD < n_b) out[(size_t)bD * GNODE + g] = oD;
    }
}

extern "C" void kernel_launch(void* const* d_in, const int* in_sizes, int n_in,
                              void* d_out, int out_size)
{
    const float* x  = (const float*)d_in[0];
    const float* W1 = (const float*)d_in[1];
    const float* B1 = (const float*)d_in[2];
    const float* W2 = (const float*)d_in[3];
    const float* B2 = (const float*)d_in[4];
    const float* W3 = (const float*)d_in[5];
    const float* B3 = (const float*)d_in[6];
    const float* W4 = (const float*)d_in[7];
    const float* B4 = (const float*)d_in[8];
    float* out = (float*)d_out;

    int n_b = in_sizes[0] / GNODE;                       // 16384
    int chunks = (n_b + TPB * PTS - 1) / (TPB * PTS);    // 16
    dim3 grid(chunks, GNODE);
    simple_network_ad_kernel<<<grid, TPB>>>(x, W1, B1, W2, B2, W3, B3, W4, B4, out, n_b);
}

// round 4
// speedup vs baseline: 1.2728x; 1.0171x over previous
#include <cuda_runtime.h>

// SimpleNetworkAD: 480 independent 1->20->20->20->1 tanh MLPs, B=16384.
// R4: weights stored in SMEM as duplicated pairs, fetched as ulonglong2
//     (LDS.128, broadcast) -> one shared load feeds 4 FFMA2s (PTS=4),
//     halving MIO traffic vs R3 and giving the scheduler room to hoist.

#define GNODE 480
#define HDIM  20
#define HD2   (HDIM / 2)
#define TPB   256
#define PTS   4              // batch points per thread (2 f32x2 packs)

typedef unsigned long long u64;

__device__ __forceinline__ u64 f2_pack(float lo, float hi) {
    u64 r; asm("mov.b64 %0, {%1, %2};" : "=l"(r) : "f"(lo), "f"(hi)); return r;
}
__device__ __forceinline__ void f2_unpack(u64 v, float& lo, float& hi) {
    asm("mov.b64 {%0, %1}, %2;" : "=f"(lo), "=f"(hi) : "l"(v));
}
__device__ __forceinline__ u64 f2_fma(u64 a, u64 b, u64 c) {
    u64 d; asm("fma.rn.f32x2 %0, %1, %2, %3;" : "=l"(d) : "l"(a), "l"(b), "l"(c)); return d;
}
__device__ __forceinline__ float tanha(float x) {
    float r; asm("tanh.approx.f32 %0, %1;" : "=f"(r) : "f"(x)); return r;
}
__device__ __forceinline__ u64 f2_tanh(u64 x) {
    float a, b; f2_unpack(x, a, b);
    return f2_pack(tanha(a), tanha(b));
}

__global__ void __launch_bounds__(TPB, 1)
simple_network_ad_kernel(const float* __restrict__ x,
                         const float* __restrict__ W1, const float* __restrict__ B1,
                         const float* __restrict__ W2, const float* __restrict__ B2,
                         const float* __restrict__ W3, const float* __restrict__ B3,
                         const float* __restrict__ W4, const float* __restrict__ B4,
                         float* __restrict__ out, int n_b)
{
    // Duplicated weight pairs packed two-at-a-time: element [k*HD2+lp] holds
    // { dup(w[k][2lp]), dup(w[k][2lp+1]) } -> single LDS.128 broadcast.
    __shared__ ulonglong2 sW1[HD2], sB1[HD2];
    __shared__ ulonglong2 sW2[HDIM * HD2];
    __shared__ ulonglong2 sW3[HDIM * HD2];
    __shared__ ulonglong2 sB2[HD2], sB3[HD2];
    __shared__ ulonglong2 sW4[HD2];
    __shared__ u64 sB4;

    const int g   = blockIdx.y;
    const int tid = threadIdx.x;

    if (tid < HD2) {
        float a, b;
        a = W1[g * HDIM + 2 * tid]; b = W1[g * HDIM + 2 * tid + 1];
        sW1[tid] = make_ulonglong2(f2_pack(a, a), f2_pack(b, b));
        a = B1[g * HDIM + 2 * tid]; b = B1[g * HDIM + 2 * tid + 1];
        sB1[tid] = make_ulonglong2(f2_pack(a, a), f2_pack(b, b));
        a = B2[g * HDIM + 2 * tid]; b = B2[g * HDIM + 2 * tid + 1];
        sB2[tid] = make_ulonglong2(f2_pack(a, a), f2_pack(b, b));
        a = B3[g * HDIM + 2 * tid]; b = B3[g * HDIM + 2 * tid + 1];
        sB3[tid] = make_ulonglong2(f2_pack(a, a), f2_pack(b, b));
        a = W4[g * HDIM + 2 * tid]; b = W4[g * HDIM + 2 * tid + 1];
        sW4[tid] = make_ulonglong2(f2_pack(a, a), f2_pack(b, b));
    }
    if (tid == 0) { float b4 = B4[g]; sB4 = f2_pack(b4, b4); }
    for (int i = tid; i < HDIM * HD2; i += TPB) {
        int k = i / HD2, lp = i % HD2;
        float a2 = W2[g * HDIM * HDIM + k * HDIM + 2 * lp];
        float b2 = W2[g * HDIM * HDIM + k * HDIM + 2 * lp + 1];
        sW2[i] = make_ulonglong2(f2_pack(a2, a2), f2_pack(b2, b2));
        float a3 = W3[g * HDIM * HDIM + k * HDIM + 2 * lp];
        float b3 = W3[g * HDIM * HDIM + k * HDIM + 2 * lp + 1];
        sW3[i] = make_ulonglong2(f2_pack(a3, a3), f2_pack(b3, b3));
    }
    __syncthreads();

    const int b0 = blockIdx.x * (TPB * PTS) + tid;
    if (b0 >= n_b) return;
    const int bA = b0;
    const int bB = b0 + TPB;
    const int bC = b0 + 2 * TPB;
    const int bD = b0 + 3 * TPB;

    float xA = x[(size_t)bA * GNODE + g];
    float xB = (bB < n_b) ? x[(size_t)bB * GNODE + g] : 0.0f;
    float xC = (bC < n_b) ? x[(size_t)bC * GNODE + g] : 0.0f;
    float xD = (bD < n_b) ? x[(size_t)bD * GNODE + g] : 0.0f;
    u64 xin0 = f2_pack(xA, xB);
    u64 xin1 = f2_pack(xC, xD);

    u64 h0[HDIM], h1[HDIM];
    u64 a0[HDIM], a1[HDIM];

    // Layer 1: h = tanh(x * W1 + b1)
    #pragma unroll
    for (int lp = 0; lp < HD2; lp++) {
        ulonglong2 w = sW1[lp], b = sB1[lp];
        h0[2 * lp]     = f2_tanh(f2_fma(xin0, w.x, b.x));
        h1[2 * lp]     = f2_tanh(f2_fma(xin1, w.x, b.x));
        h0[2 * lp + 1] = f2_tanh(f2_fma(xin0, w.y, b.y));
        h1[2 * lp + 1] = f2_tanh(f2_fma(xin1, w.y, b.y));
    }

    // Layer 2: h = tanh(h @ W2 + b2)
    #pragma unroll
    for (int lp = 0; lp < HD2; lp++) {
        ulonglong2 b = sB2[lp];
        a0[2 * lp] = b.x; a1[2 * lp] = b.x;
        a0[2 * lp + 1] = b.y; a1[2 * lp + 1] = b.y;
    }
    #pragma unroll
    for (int k = 0; k < HDIM; k++) {
        u64 hk0 = h0[k], hk1 = h1[k];
        #pragma unroll
        for (int lp = 0; lp < HD2; lp++) {
            ulonglong2 w = sW2[k * HD2 + lp];
            a0[2 * lp]     = f2_fma(hk0, w.x, a0[2 * lp]);
            a1[2 * lp]     = f2_fma(hk1, w.x, a1[2 * lp]);
            a0[2 * lp + 1] = f2_fma(hk0, w.y, a0[2 * lp + 1]);
            a1[2 * lp + 1] = f2_fma(hk1, w.y, a1[2 * lp + 1]);
        }
    }
    #pragma unroll
    for (int l = 0; l < HDIM; l++) { h0[l] = f2_tanh(a0[l]); h1[l] = f2_tanh(a1[l]); }

    // Layer 3: h = tanh(h @ W3 + b3)
    #pragma unroll
    for (int lp = 0; lp < HD2; lp++) {
        ulonglong2 b = sB3[lp];
        a0[2 * lp] = b.x; a1[2 * lp] = b.x;
        a0[2 * lp + 1] = b.y; a1[2 * lp + 1] = b.y;
    }
    #pragma unroll
    for (int k = 0; k < HDIM; k++) {
        u64 hk0 = h0[k], hk1 = h1[k];
        #pragma unroll
        for (int lp = 0; lp < HD2; lp++) {
            ulonglong2 w = sW3[k * HD2 + lp];
            a0[2 * lp]     = f2_fma(hk0, w.x, a0[2 * lp]);
            a1[2 * lp]     = f2_fma(hk1, w.x, a1[2 * lp]);
            a0[2 * lp + 1] = f2_fma(hk0, w.y, a0[2 * lp + 1]);
            a1[2 * lp + 1] = f2_fma(hk1, w.y, a1[2 * lp + 1]);
        }
    }
    #pragma unroll
    for (int l = 0; l < HDIM; l++) { h0[l] = f2_tanh(a0[l]); h1[l] = f2_tanh(a1[l]); }

    // Layer 4: out = h . W4 + b4
    u64 o0 = sB4, o1 = sB4;
    #pragma unroll
    for (int lp = 0; lp < HD2; lp++) {
        ulonglong2 w = sW4[lp];
        o0 = f2_fma(h0[2 * lp], w.x, o0);
        o1 = f2_fma(h1[2 * lp], w.x, o1);
        o0 = f2_fma(h0[2 * lp + 1], w.y, o0);
        o1 = f2_fma(h1[2 * lp + 1], w.y, o1);
    }

    float oA, oB, oC, oD;
    f2_unpack(o0, oA, oB);
    f2_unpack(o1, oC, oD);
    out[(size_t)bA * GNODE + g] = oA;
    if (bB < n_b) out[(size_t)bB * GNODE + g] = oB;
    if (bC < n_b) out[(size_t)bC * GNODE + g] = oC;
    if (bD < n_b) out[(size_t)bD * GNODE + g] = oD;
}

extern "C" void kernel_launch(void* const* d_in, const int* in_sizes, int n_in,
                              void* d_out, int out_size)
{
    const float* x  = (const float*)d_in[0];
    const float* W1 = (const float*)d_in[1];
    const float* B1 = (const float*)d_in[2];
    const float* W2 = (const float*)d_in[3];
    const float* B2 = (const float*)d_in[4];
    const float* W3 = (const float*)d_in[5];
    const float* B3 = (const float*)d_in[6];
    const float* W4 = (const float*)d_in[7];
    const float* B4 = (const float*)d_in[8];
    float* out = (float*)d_out;

    int n_b = in_sizes[0] / GNODE;                       // 16384
    int chunks = (n_b + TPB * PTS - 1) / (TPB * PTS);    // 16
    dim3 grid(chunks, GNODE);
    simple_network_ad_kernel<<<grid, TPB>>>(x, W1, B1, W2, B2, W3, B3, W4, B4, out, n_b);
}

// round 5
// speedup vs baseline: 1.5179x; 1.1926x over previous
#include <cuda_runtime.h>

// SimpleNetworkAD: 480 independent 1->20->20->20->1 tanh MLPs, B=16384.
// R5: pack f32x2 along the OUTPUT-NEURON axis {l, l+1} instead of batch.
//     Weight pairs {w[k][l], w[k][l+1]} come straight from row-major SMEM via
//     LDS.128 (no duplication, half the smem bytes of R2-R4); only h[k] is
//     duplicated (20 movs/layer vs 200). 2 batch points/thread amortize the
//     weight loads; regs ~110 -> 2 CTAs/SM (4 warps/SMSP) to hide latency.

#define GNODE 480
#define HDIM  20
#define TPB   256
#define PTS   2              // batch points per thread

typedef unsigned long long u64;

__device__ __forceinline__ u64 f2_pack(float lo, float hi) {
    u64 r; asm("mov.b64 %0, {%1, %2};" : "=l"(r) : "f"(lo), "f"(hi)); return r;
}
__device__ __forceinline__ u64 f2_dup(float v) {
    u64 r; asm("mov.b64 %0, {%1, %1};" : "=l"(r) : "f"(v)); return r;
}
__device__ __forceinline__ void f2_unpack(u64 v, float& lo, float& hi) {
    asm("mov.b64 {%0, %1}, %2;" : "=f"(lo), "=f"(hi) : "l"(v));
}
__device__ __forceinline__ u64 f2_fma(u64 a, u64 b, u64 c) {
    u64 d; asm("fma.rn.f32x2 %0, %1, %2, %3;" : "=l"(d) : "l"(a), "l"(b), "l"(c)); return d;
}
__device__ __forceinline__ float tanha(float x) {
    float r; asm("tanh.approx.f32 %0, %1;" : "=f"(r) : "f"(x)); return r;
}

__global__ void __launch_bounds__(TPB, 2)
simple_network_ad_kernel(const float* __restrict__ x,
                         const float* __restrict__ W1, const float* __restrict__ B1,
                         const float* __restrict__ W2, const float* __restrict__ B2,
                         const float* __restrict__ W3, const float* __restrict__ B3,
                         const float* __restrict__ W4, const float* __restrict__ B4,
                         float* __restrict__ out, int n_b)
{
    // Plain fp32 weights, natural row-major; rows are 80 B = 16B-aligned so
    // every W row is 5x float4.
    __shared__ __align__(16) float sW1[HDIM], sB1[HDIM];
    __shared__ __align__(16) float sW2[HDIM * HDIM], sB2[HDIM];
    __shared__ __align__(16) float sW3[HDIM * HDIM], sB3[HDIM];
    __shared__ __align__(16) float sW4[HDIM];
    __shared__ float sB4;

    const int g   = blockIdx.y;
    const int tid = threadIdx.x;

    if (tid < HDIM) {
        sW1[tid] = W1[g * HDIM + tid];
        sB1[tid] = B1[g * HDIM + tid];
        sB2[tid] = B2[g * HDIM + tid];
        sB3[tid] = B3[g * HDIM + tid];
        sW4[tid] = W4[g * HDIM + tid];
    }
    if (tid == 0) sB4 = B4[g];
    for (int i = tid; i < HDIM * HDIM; i += TPB) {
        sW2[i] = W2[g * HDIM * HDIM + i];
        sW3[i] = W3[g * HDIM * HDIM + i];
    }
    __syncthreads();

    const int b0 = blockIdx.x * (TPB * PTS) + tid;
    if (b0 >= n_b) return;
    const int b1 = b0 + TPB;

    const float4* sW1v = (const float4*)sW1;
    const float4* sB1v = (const float4*)sB1;
    const float4* sW2v = (const float4*)sW2;
    const float4* sB2v = (const float4*)sB2;
    const float4* sW3v = (const float4*)sW3;
    const float4* sB3v = (const float4*)sB3;
    const float4* sW4v = (const float4*)sW4;

    float x0 = x[(size_t)b0 * GNODE + g];
    float x1 = (b1 < n_b) ? x[(size_t)b1 * GNODE + g] : 0.0f;

    // h: 20 scalars per point.  acc: 10 neuron-pairs per point.
    float h0[HDIM], h1[HDIM];
    u64 a0[HDIM / 2], a1[HDIM / 2];

    // ---- Layer 1: h = tanh(x * W1 + b1), vector over neuron pairs ----
    {
        u64 xd0 = f2_dup(x0), xd1 = f2_dup(x1);
        #pragma unroll
        for (int q = 0; q < 5; q++) {
            float4 w = sW1v[q], b = sB1v[q];
            u64 wp0 = f2_pack(w.x, w.y), wp1 = f2_pack(w.z, w.w);
            u64 bp0 = f2_pack(b.x, b.y), bp1 = f2_pack(b.z, b.w);
            float s0, s1;
            f2_unpack(f2_fma(xd0, wp0, bp0), s0, s1);
            h0[4 * q] = tanha(s0); h0[4 * q + 1] = tanha(s1);
            f2_unpack(f2_fma(xd0, wp1, bp1), s0, s1);
            h0[4 * q + 2] = tanha(s0); h0[4 * q + 3] = tanha(s1);
            f2_unpack(f2_fma(xd1, wp0, bp0), s0, s1);
            h1[4 * q] = tanha(s0); h1[4 * q + 1] = tanha(s1);
            f2_unpack(f2_fma(xd1, wp1, bp1), s0, s1);
            h1[4 * q + 2] = tanha(s0); h1[4 * q + 3] = tanha(s1);
        }
    }

    // ---- Layer 2: h = tanh(h @ W2 + b2) ----
    #pragma unroll
    for (int q = 0; q < 5; q++) {
        float4 b = sB2v[q];
        a0[2 * q] = f2_pack(b.x, b.y); a0[2 * q + 1] = f2_pack(b.z, b.w);
        a1[2 * q] = a0[2 * q];         a1[2 * q + 1] = a0[2 * q + 1];
    }
    #pragma unroll
    for (int k = 0; k < HDIM; k++) {
        u64 hd0 = f2_dup(h0[k]), hd1 = f2_dup(h1[k]);
        #pragma unroll
        for (int q = 0; q < 5; q++) {
            float4 w = sW2v[k * 5 + q];
            u64 wp0 = f2_pack(w.x, w.y), wp1 = f2_pack(w.z, w.w);
            a0[2 * q]     = f2_fma(hd0, wp0, a0[2 * q]);
            a0[2 * q + 1] = f2_fma(hd0, wp1, a0[2 * q + 1]);
            a1[2 * q]     = f2_fma(hd1, wp0, a1[2 * q]);
            a1[2 * q + 1] = f2_fma(hd1, wp1, a1[2 * q + 1]);
        }
    }
    #pragma unroll
    for (int p = 0; p < HDIM / 2; p++) {
        float s0, s1;
        f2_unpack(a0[p], s0, s1); h0[2 * p] = tanha(s0); h0[2 * p + 1] = tanha(s1);
        f2_unpack(a1[p], s0, s1); h1[2 * p] = tanha(s0); h1[2 * p + 1] = tanha(s1);
    }

    // ---- Layer 3: h = tanh(h @ W3 + b3) ----
    #pragma unroll
    for (int q = 0; q < 5; q++) {
        float4 b = sB3v[q];
        a0[2 * q] = f2_pack(b.x, b.y); a0[2 * q + 1] = f2_pack(b.z, b.w);
        a1[2 * q] = a0[2 * q];         a1[2 * q + 1] = a0[2 * q + 1];
    }
    #pragma unroll
    for (int k = 0; k < HDIM; k++) {
        u64 hd0 = f2_dup(h0[k]), hd1 = f2_dup(h1[k]);
        #pragma unroll
        for (int q = 0; q < 5; q++) {
            float4 w = sW3v[k * 5 + q];
            u64 wp0 = f2_pack(w.x, w.y), wp1 = f2_pack(w.z, w.w);
            a0[2 * q]     = f2_fma(hd0, wp0, a0[2 * q]);
            a0[2 * q + 1] = f2_fma(hd0, wp1, a0[2 * q + 1]);
            a1[2 * q]     = f2_fma(hd1, wp0, a1[2 * q]);
            a1[2 * q + 1] = f2_fma(hd1, wp1, a1[2 * q + 1]);
        }
    }
    #pragma unroll
    for (int p = 0; p < HDIM / 2; p++) {
        float s0, s1;
        f2_unpack(a0[p], s0, s1); h0[2 * p] = tanha(s0); h0[2 * p + 1] = tanha(s1);
        f2_unpack(a1[p], s0, s1); h1[2 * p] = tanha(s0); h1[2 * p + 1] = tanha(s1);
    }

    // ---- Layer 4: out = h . W4 + b4 (pairwise dot in f32x2) ----
    u64 o0 = f2_pack(sB4, 0.0f), o1 = f2_pack(sB4, 0.0f);
    #pragma unroll
    for (int q = 0; q < 5; q++) {
        float4 w = sW4v[q];
        u64 wp0 = f2_pack(w.x, w.y), wp1 = f2_pack(w.z, w.w);
        o0 = f2_fma(f2_pack(h0[4 * q], h0[4 * q + 1]), wp0, o0);
        o0 = f2_fma(f2_pack(h0[4 * q + 2], h0[4 * q + 3]), wp1, o0);
        o1 = f2_fma(f2_pack(h1[4 * q], h1[4 * q + 1]), wp0, o1);
        o1 = f2_fma(f2_pack(h1[4 * q + 2], h1[4 * q + 3]), wp1, o1);
    }
    float oA, oB, oC, oD;
    f2_unpack(o0, oA, oB);
    f2_unpack(o1, oC, oD);
    out[(size_t)b0 * GNODE + g] = oA + oB;
    if (b1 < n_b) out[(size_t)b1 * GNODE + g] = oC + oD;
}

extern "C" void kernel_launch(void* const* d_in, const int* in_sizes, int n_in,
                              void* d_out, int out_size)
{
    const float* x  = (const float*)d_in[0];
    const float* W1 = (const float*)d_in[1];
    const float* B1 = (const float*)d_in[2];
    const float* W2 = (const float*)d_in[3];
    const float* B2 = (const float*)d_in[4];
    const float* W3 = (const float*)d_in[5];
    const float* B3 = (const float*)d_in[6];
    const float* W4 = (const float*)d_in[7];
    const float* B4 = (const float*)d_in[8];
    float* out = (float*)d_out;

    int n_b = in_sizes[0] / GNODE;                       // 16384
    int chunks = (n_b + TPB * PTS - 1) / (TPB * PTS);    // 32
    dim3 grid(chunks, GNODE);
    simple_network_ad_kernel<<<grid, TPB>>>(x, W1, B1, W2, B2, W3, B3, W4, B4, out, n_b);
}

// round 7
// speedup vs baseline: 1.5508x; 1.0217x over previous
#include <cuda_runtime.h>

// SimpleNetworkAD: 480 independent 1->20->20->20->1 tanh MLPs, B=16384.
// R7 (= R6 resubmit; R6 hit a container infra failure): R5 compute core +
//     transposed I/O. Strided x/out accesses (32 L1 wavefronts per LDG/STG)
//     were the binder in R5; pre-transpose x into xT[G,B], write outT[G,B]
//     coalesced (float2), transpose back. Scratch in __device__ globals.

#define GNODE 480
#define HDIM  20
#define TPB   256
#define PTS   2
#define BMAX  16384

typedef unsigned long long u64;

__device__ float g_xT[(size_t)GNODE * BMAX];    // x transposed   [G, B]
__device__ float g_outT[(size_t)GNODE * BMAX];  // out transposed [G, B]

__device__ __forceinline__ u64 f2_pack(float lo, float hi) {
    u64 r; asm("mov.b64 %0, {%1, %2};" : "=l"(r) : "f"(lo), "f"(hi)); return r;
}
__device__ __forceinline__ u64 f2_dup(float v) {
    u64 r; asm("mov.b64 %0, {%1, %1};" : "=l"(r) : "f"(v)); return r;
}
__device__ __forceinline__ void f2_unpack(u64 v, float& lo, float& hi) {
    asm("mov.b64 {%0, %1}, %2;" : "=f"(lo), "=f"(hi) : "l"(v));
}
__device__ __forceinline__ u64 f2_fma(u64 a, u64 b, u64 c) {
    u64 d; asm("fma.rn.f32x2 %0, %1, %2, %3;" : "=l"(d) : "l"(a), "l"(b), "l"(c)); return d;
}
__device__ __forceinline__ float tanha(float x) {
    float r; asm("tanh.approx.f32 %0, %1;" : "=f"(r) : "f"(x)); return r;
}

// ---- Transpose kernels (32x32 tiles, 32x8 threads) ----
#define TD 32
__global__ void transpose_in_kernel(const float* __restrict__ src, int n_b) {
    // src: [n_b, GNODE] -> g_xT: [GNODE, n_b]
    __shared__ float tile[TD][TD + 1];
    int g = blockIdx.x * TD + threadIdx.x;
    int b = blockIdx.y * TD + threadIdx.y;
    #pragma unroll
    for (int i = 0; i < TD; i += 8)
        if (g < GNODE && (b + i) < n_b)
            tile[threadIdx.y + i][threadIdx.x] = src[(size_t)(b + i) * GNODE + g];
    __syncthreads();
    int b2 = blockIdx.y * TD + threadIdx.x;
    int g2 = blockIdx.x * TD + threadIdx.y;
    #pragma unroll
    for (int i = 0; i < TD; i += 8)
        if (b2 < n_b && (g2 + i) < GNODE)
            g_xT[(size_t)(g2 + i) * n_b + b2] = tile[threadIdx.x][threadIdx.y + i];
}

__global__ void transpose_out_kernel(float* __restrict__ dst, int n_b) {
    // g_outT: [GNODE, n_b] -> dst: [n_b, GNODE]
    __shared__ float tile[TD][TD + 1];
    int b = blockIdx.x * TD + threadIdx.x;
    int g = blockIdx.y * TD + threadIdx.y;
    #pragma unroll
    for (int i = 0; i < TD; i += 8)
        if (b < n_b && (g + i) < GNODE)
            tile[threadIdx.y + i][threadIdx.x] = g_outT[(size_t)(g + i) * n_b + b];
    __syncthreads();
    int g2 = blockIdx.y * TD + threadIdx.x;
    int b2 = blockIdx.x * TD + threadIdx.y;
    #pragma unroll
    for (int i = 0; i < TD; i += 8)
        if (g2 < GNODE && (b2 + i) < n_b)
            dst[(size_t)(b2 + i) * GNODE + g2] = tile[threadIdx.x][threadIdx.y + i];
}

// ---- Fallback: R5-style kernel reading/writing strided layouts directly.
//      Used only if n_b > BMAX (scratch too small). Same math.
__global__ void __launch_bounds__(TPB, 2)
simple_network_ad_direct(const float* __restrict__ x,
                         const float* __restrict__ W1, const float* __restrict__ B1,
                         const float* __restrict__ W2, const float* __restrict__ B2,
                         const float* __restrict__ W3, const float* __restrict__ B3,
                         const float* __restrict__ W4, const float* __restrict__ B4,
                         float* __restrict__ out, int n_b);

// ---- Main compute: f32x2 packed along output-neuron axis, coalesced I/O ----
__global__ void __launch_bounds__(TPB, 2)
simple_network_ad_kernel(const float* __restrict__ W1, const float* __restrict__ B1,
                         const float* __restrict__ W2, const float* __restrict__ B2,
                         const float* __restrict__ W3, const float* __restrict__ B3,
                         const float* __restrict__ W4, const float* __restrict__ B4,
                         int n_b)
{
    __shared__ __align__(16) float sW1[HDIM], sB1[HDIM];
    __shared__ __align__(16) float sW2[HDIM * HDIM], sB2[HDIM];
    __shared__ __align__(16) float sW3[HDIM * HDIM], sB3[HDIM];
    __shared__ __align__(16) float sW4[HDIM];
    __shared__ float sB4;

    const int g   = blockIdx.y;
    const int tid = threadIdx.x;

    if (tid < HDIM) {
        sW1[tid] = W1[g * HDIM + tid];
        sB1[tid] = B1[g * HDIM + tid];
        sB2[tid] = B2[g * HDIM + tid];
        sB3[tid] = B3[g * HDIM + tid];
        sW4[tid] = W4[g * HDIM + tid];
    }
    if (tid == 0) sB4 = B4[g];
    for (int i = tid; i < HDIM * HDIM; i += TPB) {
        sW2[i] = W2[g * HDIM * HDIM + i];
        sW3[i] = W3[g * HDIM * HDIM + i];
    }
    __syncthreads();

    const int b0 = (blockIdx.x * TPB + tid) * PTS;   // consecutive pair b0, b0+1
    if (b0 >= n_b) return;
    const int b1 = b0 + 1;

    const float4* sW1v = (const float4*)sW1;
    const float4* sB1v = (const float4*)sB1;
    const float4* sW2v = (const float4*)sW2;
    const float4* sB2v = (const float4*)sB2;
    const float4* sW3v = (const float4*)sW3;
    const float4* sB3v = (const float4*)sB3;
    const float4* sW4v = (const float4*)sW4;

    float x0, x1;
    if (b1 < n_b) {
        float2 v = *(const float2*)&g_xT[(size_t)g * n_b + b0];
        x0 = v.x; x1 = v.y;
    } else {
        x0 = g_xT[(size_t)g * n_b + b0]; x1 = 0.0f;
    }

    float h0[HDIM], h1[HDIM];
    u64 a0[HDIM / 2], a1[HDIM / 2];

    // ---- Layer 1 ----
    {
        u64 xd0 = f2_dup(x0), xd1 = f2_dup(x1);
        #pragma unroll
        for (int q = 0; q < 5; q++) {
            float4 w = sW1v[q], b = sB1v[q];
            u64 wp0 = f2_pack(w.x, w.y), wp1 = f2_pack(w.z, w.w);
            u64 bp0 = f2_pack(b.x, b.y), bp1 = f2_pack(b.z, b.w);
            float s0, s1;
            f2_unpack(f2_fma(xd0, wp0, bp0), s0, s1);
            h0[4 * q] = tanha(s0); h0[4 * q + 1] = tanha(s1);
            f2_unpack(f2_fma(xd0, wp1, bp1), s0, s1);
            h0[4 * q + 2] = tanha(s0); h0[4 * q + 3] = tanha(s1);
            f2_unpack(f2_fma(xd1, wp0, bp0), s0, s1);
            h1[4 * q] = tanha(s0); h1[4 * q + 1] = tanha(s1);
            f2_unpack(f2_fma(xd1, wp1, bp1), s0, s1);
            h1[4 * q + 2] = tanha(s0); h1[4 * q + 3] = tanha(s1);
        }
    }

    // ---- Layer 2 ----
    #pragma unroll
    for (int q = 0; q < 5; q++) {
        float4 b = sB2v[q];
        a0[2 * q] = f2_pack(b.x, b.y); a0[2 * q + 1] = f2_pack(b.z, b.w);
        a1[2 * q] = a0[2 * q];         a1[2 * q + 1] = a0[2 * q + 1];
    }
    #pragma unroll
    for (int k = 0; k < HDIM; k++) {
        u64 hd0 = f2_dup(h0[k]), hd1 = f2_dup(h1[k]);
        #pragma unroll
        for (int q = 0; q < 5; q++) {
            float4 w = sW2v[k * 5 + q];
            u64 wp0 = f2_pack(w.x, w.y), wp1 = f2_pack(w.z, w.w);
            a0[2 * q]     = f2_fma(hd0, wp0, a0[2 * q]);
            a0[2 * q + 1] = f2_fma(hd0, wp1, a0[2 * q + 1]);
            a1[2 * q]     = f2_fma(hd1, wp0, a1[2 * q]);
            a1[2 * q + 1] = f2_fma(hd1, wp1, a1[2 * q + 1]);
        }
    }
    #pragma unroll
    for (int p = 0; p < HDIM / 2; p++) {
        float s0, s1;
        f2_unpack(a0[p], s0, s1); h0[2 * p] = tanha(s0); h0[2 * p + 1] = tanha(s1);
        f2_unpack(a1[p], s0, s1); h1[2 * p] = tanha(s0); h1[2 * p + 1] = tanha(s1);
    }

    // ---- Layer 3 ----
    #pragma unroll
    for (int q = 0; q < 5; q++) {
        float4 b = sB3v[q];
        a0[2 * q] = f2_pack(b.x, b.y); a0[2 * q + 1] = f2_pack(b.z, b.w);
        a1[2 * q] = a0[2 * q];         a1[2 * q + 1] = a0[2 * q + 1];
    }
    #pragma unroll
    for (int k = 0; k < HDIM; k++) {
        u64 hd0 = f2_dup(h0[k]), hd1 = f2_dup(h1[k]);
        #pragma unroll
        for (int q = 0; q < 5; q++) {
            float4 w = sW3v[k * 5 + q];
            u64 wp0 = f2_pack(w.x, w.y), wp1 = f2_pack(w.z, w.w);
            a0[2 * q]     = f2_fma(hd0, wp0, a0[2 * q]);
            a0[2 * q + 1] = f2_fma(hd0, wp1, a0[2 * q + 1]);
            a1[2 * q]     = f2_fma(hd1, wp0, a1[2 * q]);
            a1[2 * q + 1] = f2_fma(hd1, wp1, a1[2 * q + 1]);
        }
    }
    #pragma unroll
    for (int p = 0; p < HDIM / 2; p++) {
        float s0, s1;
        f2_unpack(a0[p], s0, s1); h0[2 * p] = tanha(s0); h0[2 * p + 1] = tanha(s1);
        f2_unpack(a1[p], s0, s1); h1[2 * p] = tanha(s0); h1[2 * p + 1] = tanha(s1);
    }

    // ---- Layer 4 ----
    u64 o0 = f2_pack(sB4, 0.0f), o1 = f2_pack(sB4, 0.0f);
    #pragma unroll
    for (int q = 0; q < 5; q++) {
        float4 w = sW4v[q];
        u64 wp0 = f2_pack(w.x, w.y), wp1 = f2_pack(w.z, w.w);
        o0 = f2_fma(f2_pack(h0[4 * q], h0[4 * q + 1]), wp0, o0);
        o0 = f2_fma(f2_pack(h0[4 * q + 2], h0[4 * q + 3]), wp1, o0);
        o1 = f2_fma(f2_pack(h1[4 * q], h1[4 * q + 1]), wp0, o1);
        o1 = f2_fma(f2_pack(h1[4 * q + 2], h1[4 * q + 3]), wp1, o1);
    }
    float oA, oB, oC, oD;
    f2_unpack(o0, oA, oB);
    f2_unpack(o1, oC, oD);
    if (b1 < n_b) {
        float2 v; v.x = oA + oB; v.y = oC + oD;
        *(float2*)&g_outT[(size_t)g * n_b + b0] = v;
    } else {
        g_outT[(size_t)g * n_b + b0] = oA + oB;
    }
}

// ---- Fallback definition (strided I/O, R5 logic) ----
__global__ void __launch_bounds__(TPB, 2)
simple_network_ad_direct(const float* __restrict__ x,
                         const float* __restrict__ W1, const float* __restrict__ B1,
                         const float* __restrict__ W2, const float* __restrict__ B2,
                         const float* __restrict__ W3, const float* __restrict__ B3,
                         const float* __restrict__ W4, const float* __restrict__ B4,
                         float* __restrict__ out, int n_b)
{
    __shared__ __align__(16) float sW1[HDIM], sB1[HDIM];
    __shared__ __align__(16) float sW2[HDIM * HDIM], sB2[HDIM];
    __shared__ __align__(16) float sW3[HDIM * HDIM], sB3[HDIM];
    __shared__ __align__(16) float sW4[HDIM];
    __shared__ float sB4;

    const int g   = blockIdx.y;
    const int tid = threadIdx.x;

    if (tid < HDIM) {
        sW1[tid] = W1[g * HDIM + tid];
        sB1[tid] = B1[g * HDIM + tid];
        sB2[tid] = B2[g * HDIM + tid];
        sB3[tid] = B3[g * HDIM + tid];
        sW4[tid] = W4[g * HDIM + tid];
    }
    if (tid == 0) sB4 = B4[g];
    for (int i = tid; i < HDIM * HDIM; i += TPB) {
        sW2[i] = W2[g * HDIM * HDIM + i];
        sW3[i] = W3[g * HDIM * HDIM + i];
    }
    __syncthreads();

    const int b0 = blockIdx.x * (TPB * PTS) + tid;
    if (b0 >= n_b) return;
    const int b1 = b0 + TPB;

    const float4* sW1v = (const float4*)sW1;
    const float4* sB1v = (const float4*)sB1;
    const float4* sW2v = (const float4*)sW2;
    const float4* sB2v = (const float4*)sB2;
    const float4* sW3v = (const float4*)sW3;
    const float4* sB3v = (const float4*)sB3;
    const float4* sW4v = (const float4*)sW4;

    float x0 = x[(size_t)b0 * GNODE + g];
    float x1 = (b1 < n_b) ? x[(size_t)b1 * GNODE + g] : 0.0f;

    float h0[HDIM], h1[HDIM];
    u64 a0[HDIM / 2], a1[HDIM / 2];

    {
        u64 xd0 = f2_dup(x0), xd1 = f2_dup(x1);
        #pragma unroll
        for (int q = 0; q < 5; q++) {
            float4 w = sW1v[q], b = sB1v[q];
            u64 wp0 = f2_pack(w.x, w.y), wp1 = f2_pack(w.z, w.w);
            u64 bp0 = f2_pack(b.x, b.y), bp1 = f2_pack(b.z, b.w);
            float s0, s1;
            f2_unpack(f2_fma(xd0, wp0, bp0), s0, s1);
            h0[4 * q] = tanha(s0); h0[4 * q + 1] = tanha(s1);
            f2_unpack(f2_fma(xd0, wp1, bp1), s0, s1);
            h0[4 * q + 2] = tanha(s0); h0[4 * q + 3] = tanha(s1);
            f2_unpack(f2_fma(xd1, wp0, bp0), s0, s1);
            h1[4 * q] = tanha(s0); h1[4 * q + 1] = tanha(s1);
            f2_unpack(f2_fma(xd1, wp1, bp1), s0, s1);
            h1[4 * q + 2] = tanha(s0); h1[4 * q + 3] = tanha(s1);
        }
    }

    #pragma unroll
    for (int q = 0; q < 5; q++) {
        float4 b = sB2v[q];
        a0[2 * q] = f2_pack(b.x, b.y); a0[2 * q + 1] = f2_pack(b.z, b.w);
        a1[2 * q] = a0[2 * q];         a1[2 * q + 1] = a0[2 * q + 1];
    }
    #pragma unroll
    for (int k = 0; k < HDIM; k++) {
        u64 hd0 = f2_dup(h0[k]), hd1 = f2_dup(h1[k]);
        #pragma unroll
        for (int q = 0; q < 5; q++) {
            float4 w = sW2v[k * 5 + q];
            u64 wp0 = f2_pack(w.x, w.y), wp1 = f2_pack(w.z, w.w);
            a0[2 * q]     = f2_fma(hd0, wp0, a0[2 * q]);
            a0[2 * q + 1] = f2_fma(hd0, wp1, a0[2 * q + 1]);
            a1[2 * q]     = f2_fma(hd1, wp0, a1[2 * q]);
            a1[2 * q + 1] = f2_fma(hd1, wp1, a1[2 * q + 1]);
        }
    }
    #pragma unroll
    for (int p = 0; p < HDIM / 2; p++) {
        float s0, s1;
        f2_unpack(a0[p], s0, s1); h0[2 * p] = tanha(s0); h0[2 * p + 1] = tanha(s1);
        f2_unpack(a1[p], s0, s1); h1[2 * p] = tanha(s0); h1[2 * p + 1] = tanha(s1);
    }

    #pragma unroll
    for (int q = 0; q < 5; q++) {
        float4 b = sB3v[q];
        a0[2 * q] = f2_pack(b.x, b.y); a0[2 * q + 1] = f2_pack(b.z, b.w);
        a1[2 * q] = a0[2 * q];         a1[2 * q + 1] = a0[2 * q + 1];
    }
    #pragma unroll
    for (int k = 0; k < HDIM; k++) {
        u64 hd0 = f2_dup(h0[k]), hd1 = f2_dup(h1[k]);
        #pragma unroll
        for (int q = 0; q < 5; q++) {
            float4 w = sW3v[k * 5 + q];
            u64 wp0 = f2_pack(w.x, w.y), wp1 = f2_pack(w.z, w.w);
            a0[2 * q]     = f2_fma(hd0, wp0, a0[2 * q]);
            a0[2 * q + 1] = f2_fma(hd0, wp1, a0[2 * q + 1]);
            a1[2 * q]     = f2_fma(hd1, wp0, a1[2 * q]);
            a1[2 * q + 1] = f2_fma(hd1, wp1, a1[2 * q + 1]);
        }
    }
    #pragma unroll
    for (int p = 0; p < HDIM / 2; p++) {
        float s0, s1;
        f2_unpack(a0[p], s0, s1); h0[2 * p] = tanha(s0); h0[2 * p + 1] = tanha(s1);
        f2_unpack(a1[p], s0, s1); h1[2 * p] = tanha(s0); h1[2 * p + 1] = tanha(s1);
    }

    u64 o0 = f2_pack(sB4, 0.0f), o1 = f2_pack(sB4, 0.0f);
    #pragma unroll
    for (int q = 0; q < 5; q++) {
        float4 w = sW4v[q];
        u64 wp0 = f2_pack(w.x, w.y), wp1 = f2_pack(w.z, w.w);
        o0 = f2_fma(f2_pack(h0[4 * q], h0[4 * q + 1]), wp0, o0);
        o0 = f2_fma(f2_pack(h0[4 * q + 2], h0[4 * q + 3]), wp1, o0);
        o1 = f2_fma(f2_pack(h1[4 * q], h1[4 * q + 1]), wp0, o1);
        o1 = f2_fma(f2_pack(h1[4 * q + 2], h1[4 * q + 3]), wp1, o1);
    }
    float oA, oB, oC, oD;
    f2_unpack(o0, oA, oB);
    f2_unpack(o1, oC, oD);
    out[(size_t)b0 * GNODE + g] = oA + oB;
    if (b1 < n_b) out[(size_t)b1 * GNODE + g] = oC + oD;
}

extern "C" void kernel_launch(void* const* d_in, const int* in_sizes, int n_in,
                              void* d_out, int out_size)
{
    const float* x  = (const float*)d_in[0];
    const float* W1 = (const float*)d_in[1];
    const float* B1 = (const float*)d_in[2];
    const float* W2 = (const float*)d_in[3];
    const float* B2 = (const float*)d_in[4];
    const float* W3 = (const float*)d_in[5];
    const float* B3 = (const float*)d_in[6];
    const float* W4 = (const float*)d_in[7];
    const float* B4 = (const float*)d_in[8];
    float* out = (float*)d_out;

    int n_b = in_sizes[0] / GNODE;                      // 16384

    if (n_b <= BMAX) {
        // A: transpose x -> xT
        dim3 tgrid_in((GNODE + TD - 1) / TD, (n_b + TD - 1) / TD);
        transpose_in_kernel<<<tgrid_in, dim3(TD, 8)>>>(x, n_b);

        // B: compute on transposed layout
        int chunks = (n_b + TPB * PTS - 1) / (TPB * PTS);
        dim3 grid(chunks, GNODE);
        simple_network_ad_kernel<<<grid, TPB>>>(W1, B1, W2, B2, W3, B3, W4, B4, n_b);

        // C: transpose outT -> out
        dim3 tgrid_out((n_b + TD - 1) / TD, (GNODE + TD - 1) / TD);
        transpose_out_kernel<<<tgrid_out, dim3(TD, 8)>>>(out, n_b);
    } else {
        int chunks = (n_b + TPB * PTS - 1) / (TPB * PTS);
        dim3 grid(chunks, GNODE);
        simple_network_ad_direct<<<grid, TPB>>>(x, W1, B1, W2, B2, W3, B3, W4, B4, out, n_b);
    }
}